// round 13
// baseline (speedup 1.0000x reference)
#include <cuda_runtime.h>
#include <cuda_bf16.h>
#include <stdint.h>

#define M_TOT 16384
#define HDIM_ 2048
#define IDIM_ 512
#define ODIM_ 512

// device-global scratch (no allocs allowed)
__device__ float         g_h  [(size_t)M_TOT * HDIM_];   // approx encoder output
__device__ __nv_bfloat16 g_hb0[(size_t)M_TOT * HDIM_];
__device__ __nv_bfloat16 g_hb1[(size_t)M_TOT * HDIM_];
__device__ __nv_bfloat16 g_xb0[(size_t)M_TOT * IDIM_];
__device__ __nv_bfloat16 g_xb1[(size_t)M_TOT * IDIM_];
__device__ __nv_bfloat16 g_we0[(size_t)HDIM_ * IDIM_];
__device__ __nv_bfloat16 g_we1[(size_t)HDIM_ * IDIM_];
__device__ __nv_bfloat16 g_wd0[(size_t)ODIM_ * HDIM_];
__device__ __nv_bfloat16 g_wd1[(size_t)ODIM_ * HDIM_];

__device__ __forceinline__ uint32_t smem_u32(const void* p){
    uint32_t a;
    asm("{ .reg .u64 t; cvta.to.shared.u64 t, %1; cvt.u32.u64 %0, t; }" : "=r"(a) : "l"(p));
    return a;
}
#define CP16(d, s) asm volatile("cp.async.cg.shared.global [%0], [%1], 16;" :: "r"(d), "l"(s))
#define CP_COMMIT() asm volatile("cp.async.commit_group;")
#define CP_WAIT0()  asm volatile("cp.async.wait_group 0;")

#define LDSM4(r, a) \
    asm volatile("ldmatrix.sync.aligned.m8n8.x4.shared.b16 {%0,%1,%2,%3}, [%4];" \
        : "=r"((r)[0]), "=r"((r)[1]), "=r"((r)[2]), "=r"((r)[3]) : "r"(a))

__device__ __forceinline__ void mma_bf16(float* c, const uint32_t* a, uint32_t b0, uint32_t b1){
    asm volatile("mma.sync.aligned.m16n8k16.row.col.f32.bf16.bf16.f32 "
        "{%0,%1,%2,%3},{%4,%5,%6,%7},{%8,%9},{%0,%1,%2,%3};"
        : "+f"(c[0]), "+f"(c[1]), "+f"(c[2]), "+f"(c[3])
        : "r"(a[0]), "r"(a[1]), "r"(a[2]), "r"(a[3]), "r"(b0), "r"(b1));
}

static constexpr int LDTH    = 40;            // halfs per smem row (32 + 8 pad)
static constexpr int PLANE_H = 128 * LDTH;
static constexpr int PLANE_B = PLANE_H * 2;
static constexpr int STAGE_B = 4 * PLANE_B;   // A0,A1,B0,B1 = 40960 B
static constexpr int BIAS_B  = 2 * STAGE_B;   // 2 stages
static constexpr int SMEM_GG = BIAS_B + 512;  // 82432 B -> 2 CTAs/SM
static constexpr int PERSIST = 296;           // 148 SMs x 2 CTAs

// C[M,N] = (A0+A1)[M,K] * (B0+B1)[N,K]^T + bias[N]; 3-product bf16 mma.
// Persistent CTAs: each block loops over 128x128 tiles with stride gridDim.x
// (kills wave-quantization tail). Per-tile mainloop identical to R12:
// single __syncthreads per K-chunk, 2-stage cp.async, 2 CTAs/SM.
// mma order identical to R8-R12 (bit-identical results).
template<bool EPI_MASK>
__global__ __launch_bounds__(256, 2)
void gemm_bf3(const __nv_bfloat16* __restrict__ A0, const __nv_bfloat16* __restrict__ A1,
              const __nv_bfloat16* __restrict__ B0, const __nv_bfloat16* __restrict__ B1,
              const float* __restrict__ bias, const int* __restrict__ maskPrev,
              float* __restrict__ C, int M, int N, int K)
{
    extern __shared__ char smem[];
    const uint32_t sb = smem_u32(smem);
    const int tid = threadIdx.x;
    const int lane = tid & 31, wid = tid >> 5;
    const int wm = wid & 3, wn = wid >> 2;        // 4 m-warps x 2 n-warps (32x64 warp tile)
    const int g = lane >> 2, t4 = lane & 3;

    float* sbias = (float*)(smem + BIAS_B);

    const int lr  = tid >> 1;
    const int lcb = (tid & 1) * 32;
    const uint32_t dof = (uint32_t)(lr * (LDTH * 2) + lcb);

    // ldmatrix lane address components (tile-invariant)
    const int a_r = ((lane >> 3) & 1) * 8 + (lane & 7);
    const int a_c = (lane >> 4) * 8;
    const int b_r = (lane >> 4) * 8 + (lane & 7);
    const int b_c = ((lane >> 3) & 1) * 8;
    uint32_t aoff[2][2], boff[2][4];
#pragma unroll
    for (int p = 0; p < 2; ++p) {
#pragma unroll
        for (int mt = 0; mt < 2; ++mt)
            aoff[p][mt] = (uint32_t)((p * PLANE_H + (wm * 32 + mt * 16 + a_r) * LDTH + a_c) * 2);
#pragma unroll
        for (int nt2 = 0; nt2 < 4; ++nt2)
            boff[p][nt2] = (uint32_t)(((2 + p) * PLANE_H + (wn * 64 + nt2 * 16 + b_r) * LDTH + b_c) * 2);
    }

    const int KT  = K >> 5;
    const int ntx = N >> 7;                      // tiles along N
    const int tiles = (M >> 7) * ntx;

    for (int t = blockIdx.x; t < tiles; t += gridDim.x) {
        const int m0 = (t / ntx) * 128, n0 = (t % ntx) * 128;

        __syncthreads();                         // smem/bias reuse from previous tile
        if (tid < 128) sbias[tid] = bias[n0 + tid];

        const __nv_bfloat16* pA0 = A0 + (size_t)(m0 + lr) * K;
        const __nv_bfloat16* pA1 = A1 + (size_t)(m0 + lr) * K;
        const __nv_bfloat16* pB0 = B0 + (size_t)(n0 + lr) * K;
        const __nv_bfloat16* pB1 = B1 + (size_t)(n0 + lr) * K;

        auto load_stage = [&](int kt, int s) {
            const uint32_t base = sb + (uint32_t)(s * STAGE_B) + dof;
            const int ko = kt * 32 + (lcb >> 1);
            CP16(base,               pA0 + ko); CP16(base + 16,               pA0 + ko + 8);
            CP16(base + PLANE_B,     pA1 + ko); CP16(base + PLANE_B + 16,     pA1 + ko + 8);
            CP16(base + 2 * PLANE_B, pB0 + ko); CP16(base + 2 * PLANE_B + 16, pB0 + ko + 8);
            CP16(base + 3 * PLANE_B, pB1 + ko); CP16(base + 3 * PLANE_B + 16, pB1 + ko + 8);
        };

        float acc[2][8][4];
#pragma unroll
        for (int a = 0; a < 2; ++a)
#pragma unroll
            for (int b = 0; b < 8; ++b)
#pragma unroll
                for (int q = 0; q < 4; ++q) acc[a][b][q] = 0.f;

        load_stage(0, 0); CP_COMMIT();

        for (int kt = 0; kt < KT; ++kt) {
            const int s = kt & 1;
            CP_WAIT0();
            __syncthreads();
            if (kt + 1 < KT) load_stage(kt + 1, s ^ 1);
            CP_COMMIT();
            const uint32_t stu = sb + (uint32_t)(s * STAGE_B);
#pragma unroll
            for (int ks = 0; ks < 2; ++ks) {
                uint32_t af[2][2][4];
#pragma unroll
                for (int p = 0; p < 2; ++p)
#pragma unroll
                    for (int mt = 0; mt < 2; ++mt)
                        LDSM4(af[p][mt], stu + aoff[p][mt] + ks * 32);
#pragma unroll
                for (int nt2 = 0; nt2 < 4; ++nt2) {
                    uint32_t b0r[4], b1r[4];
                    LDSM4(b0r, stu + boff[0][nt2] + ks * 32);
                    LDSM4(b1r, stu + boff[1][nt2] + ks * 32);
#pragma unroll
                    for (int h = 0; h < 2; ++h) {
                        const int nt = 2 * nt2 + h;
                        const uint32_t b00 = b0r[2 * h], b01 = b0r[2 * h + 1];
                        const uint32_t b10 = b1r[2 * h], b11 = b1r[2 * h + 1];
#pragma unroll
                        for (int mt = 0; mt < 2; ++mt) {
                            mma_bf16(acc[mt][nt], af[0][mt], b00, b01);  // a0*b0
                            mma_bf16(acc[mt][nt], af[0][mt], b10, b11);  // a0*b1
                            mma_bf16(acc[mt][nt], af[1][mt], b00, b01);  // a1*b0
                        }
                    }
                }
            }
        }

#pragma unroll
        for (int mt = 0; mt < 2; ++mt) {
#pragma unroll
            for (int nt = 0; nt < 8; ++nt) {
                const int rr = m0 + wm * 32 + mt * 16 + g;
                const int cl = wn * 64 + nt * 8 + 2 * t4;
                const float b0 = sbias[cl];
                const float b1 = sbias[cl + 1];
                const float* c = acc[mt][nt];
                float2 v0 = make_float2(c[0] + b0, c[1] + b1);
                float2 v1 = make_float2(c[2] + b0, c[3] + b1);
                const size_t i0 = (size_t)rr * N + (n0 + cl);
                const size_t i1 = (size_t)(rr + 8) * N + (n0 + cl);
                if (EPI_MASK) {
                    const int2 q0 = *(const int2*)(maskPrev + i0);
                    const int2 q1 = *(const int2*)(maskPrev + i1);
                    if (q0.x > 0) v0.x = 0.f;
                    if (q0.y > 0) v0.y = 0.f;
                    if (q1.x > 0) v1.x = 0.f;
                    if (q1.y > 0) v1.y = 0.f;
                }
                *(float2*)(C + i0) = v0;
                *(float2*)(C + i1) = v1;
            }
        }
    }
}

// fused fp32 -> 2-plane bf16 split for x, W_enc, W_dec in one launch
__global__ __launch_bounds__(256)
void split_all(const float* __restrict__ x,  __nv_bfloat16* __restrict__ xb0, __nv_bfloat16* __restrict__ xb1,
               const float* __restrict__ we, __nv_bfloat16* __restrict__ we0, __nv_bfloat16* __restrict__ we1,
               const float* __restrict__ wd, __nv_bfloat16* __restrict__ wd0, __nv_bfloat16* __restrict__ wd1)
{
    const int b = blockIdx.x;
    const float* src;
    __nv_bfloat16 *p0, *p1;
    int i;
    if (b < 4096)      { src = x;  p0 = xb0; p1 = xb1; i = b * 256 + threadIdx.x; }
    else if (b < 4608) { src = we; p0 = we0; p1 = we1; i = (b - 4096) * 256 + threadIdx.x; }
    else               { src = wd; p0 = wd0; p1 = wd1; i = (b - 4608) * 256 + threadIdx.x; }
    float4 v0 = ((const float4*)src)[2 * i];
    float4 v1 = ((const float4*)src)[2 * i + 1];
    float xv[8] = {v0.x, v0.y, v0.z, v0.w, v1.x, v1.y, v1.z, v1.w};
    __nv_bfloat16 b0[8], b1[8];
#pragma unroll
    for (int j = 0; j < 8; ++j) {
        b0[j] = __float2bfloat16_rn(xv[j]);
        b1[j] = __float2bfloat16_rn(xv[j] - __bfloat162float(b0[j]));
    }
    ((uint4*)p0)[i] = *(uint4*)b0;
    ((uint4*)p1)[i] = *(uint4*)b1;
}

// ---------------------------------------------------------------------------
// Dual top-k (512/256) over approx h^2 with epsilon-band exact repair.
// Joint radix on the top 24 bits (3 passes); threshold truncation <= 2^-16
// relative is absorbed by the 1e-3 band, which is repaired exactly.
// ---------------------------------------------------------------------------
static constexpr int CAP = 64;

__global__ __launch_bounds__(256)
void topk_band(const int* __restrict__ maskPrev, float* __restrict__ maskNew,
               const float* __restrict__ x, const float* __restrict__ W_enc,
               const float* __restrict__ b_enc)
{
    __shared__ unsigned s_hist[512];     // [0:256) sel0, [256:512) sel1
    __shared__ unsigned s_warp[8];
    __shared__ unsigned s_wsuf[8];
    __shared__ unsigned s_pick0[2];
    __shared__ unsigned s_pick1[2];
    __shared__ float    s_x[IDIM_];
    __shared__ int      s_cidx[CAP];
    __shared__ float    s_cv2[CAP];
    __shared__ int      s_csel[CAP];
    __shared__ int      s_ccnt;
    __shared__ int      s_need[2];

    const int row = blockIdx.x, tid = threadIdx.x;
    const int lane = tid & 31, wid = tid >> 5;
    const float* __restrict__ hrow = g_h + (size_t)row * HDIM_;

    float v[8], v2[8]; unsigned u[8];
    *(float4*)&v[0] = *(const float4*)&hrow[tid * 8];
    *(float4*)&v[4] = *(const float4*)&hrow[tid * 8 + 4];
#pragma unroll
    for (int j = 0; j < 8; ++j) { v2[j] = v[j] * v[j]; u[j] = __float_as_uint(v2[j]); }

    s_x[tid]       = x[(size_t)row * IDIM_ + tid];
    s_x[tid + 256] = x[(size_t)row * IDIM_ + tid + 256];
    if (tid == 0) s_ccnt = 0;

    unsigned prefix0, prefix1, kk0, kk1, pmask;

    // ---- pass 0 (shared histogram, top byte), joint pick for k=512 and k=256
    s_hist[tid] = 0u;
    __syncthreads();
#pragma unroll
    for (int j = 0; j < 8; ++j) atomicAdd(&s_hist[u[j] >> 24], 1u);
    __syncthreads();
    {
        const unsigned cnt = s_hist[tid];
        unsigned suf = cnt;
#pragma unroll
        for (int off = 1; off < 32; off <<= 1) {
            unsigned t = __shfl_down_sync(0xffffffffu, suf, off);
            if (lane + off < 32) suf += t;
        }
        const unsigned wtot = __shfl_sync(0xffffffffu, suf, 0);
        if (lane == 0) s_warp[wid] = wtot;
        __syncthreads();
        if (tid < 8) {
            unsigned s = 0;
            for (int w = tid + 1; w < 8; ++w) s += s_warp[w];
            s_wsuf[tid] = s;
        }
        __syncthreads();
        suf += s_wsuf[wid];
        if (suf >= 512u && suf - cnt < 512u) { s_pick0[0] = (unsigned)tid; s_pick0[1] = 512u - (suf - cnt); }
        if (suf >= 256u && suf - cnt < 256u) { s_pick1[0] = (unsigned)tid; s_pick1[1] = 256u - (suf - cnt); }
        __syncthreads();
        prefix0 = s_pick0[0] << 24; kk0 = s_pick0[1];
        prefix1 = s_pick1[0] << 24; kk1 = s_pick1[1];
        pmask = 255u << 24;
    }

    // ---- passes 1..2: joint dual histograms, packed 16|16 scan (bits [23:8])
#pragma unroll 1
    for (int pass = 1; pass < 3; ++pass) {
        const int shift = 24 - 8 * pass;
        __syncthreads();
        s_hist[tid] = 0u; s_hist[tid + 256] = 0u;
        __syncthreads();
#pragma unroll
        for (int j = 0; j < 8; ++j) {
            if ((u[j] & pmask) == prefix0) atomicAdd(&s_hist[(u[j] >> shift) & 255u], 1u);
            if ((u[j] & pmask) == prefix1) atomicAdd(&s_hist[256u + ((u[j] >> shift) & 255u)], 1u);
        }
        __syncthreads();
        const unsigned cnt0 = s_hist[tid], cnt1 = s_hist[tid + 256];
        unsigned suf = (cnt0 << 16) | cnt1;
#pragma unroll
        for (int off = 1; off < 32; off <<= 1) {
            unsigned t = __shfl_down_sync(0xffffffffu, suf, off);
            if (lane + off < 32) suf += t;
        }
        const unsigned wtot = __shfl_sync(0xffffffffu, suf, 0);
        if (lane == 0) s_warp[wid] = wtot;
        __syncthreads();
        if (tid < 8) {
            unsigned s = 0;
            for (int w = tid + 1; w < 8; ++w) s += s_warp[w];
            s_wsuf[tid] = s;
        }
        __syncthreads();
        suf += s_wsuf[wid];
        const unsigned suf0 = suf >> 16, suf1 = suf & 0xFFFFu;
        if (suf0 >= kk0 && suf0 - cnt0 < kk0) { s_pick0[0] = (unsigned)tid; s_pick0[1] = kk0 - (suf0 - cnt0); }
        if (suf1 >= kk1 && suf1 - cnt1 < kk1) { s_pick1[0] = (unsigned)tid; s_pick1[1] = kk1 - (suf1 - cnt1); }
        __syncthreads();
        prefix0 |= s_pick0[0] << shift; kk0 = s_pick0[1];
        prefix1 |= s_pick1[0] << shift; kk1 = s_pick1[1];
        pmask  |= 255u << shift;
    }
    __syncthreads();

    // T truncated to top-24 bits: T_hat <= T_true, relative gap <= 2^-16.
    const float T0 = __uint_as_float(prefix0), T1 = __uint_as_float(prefix1);
    const float e0 = T0 * 1e-3f, e1 = T1 * 1e-3f;

    // collect band candidates
    int lpos[8];
#pragma unroll
    for (int j = 0; j < 8; ++j) {
        lpos[j] = -1;
        const bool cand = (fabsf(v2[j] - T0) <= e0) || (fabsf(v2[j] - T1) <= e1);
        if (cand) {
            int p = atomicAdd(&s_ccnt, 1);
            if (p < CAP) { s_cidx[p] = tid * 8 + j; lpos[j] = p; }
        }
    }
    __syncthreads();
    const int nC = min(s_ccnt, CAP);

    // exact recompute of candidates (one warp per candidate, round-robin)
    for (int c = wid; c < nC; c += 8) {
        const int ch = s_cidx[c];
        const float* wr = W_enc + (size_t)ch * IDIM_;
        float s = 0.f;
#pragma unroll 4
        for (int k2 = lane; k2 < IDIM_; k2 += 32) s = fmaf(s_x[k2], wr[k2], s);
#pragma unroll
        for (int off = 16; off > 0; off >>= 1) s += __shfl_down_sync(0xffffffffu, s, off);
        if (lane == 0) {
            float hex = s + b_enc[ch];
            if (maskPrev[(size_t)row * HDIM_ + ch] > 0) hex = 0.f;
            s_cv2[c] = hex * hex;
        }
    }
    __syncthreads();

    // count definite-ins among non-candidates (packed 16|16)
    unsigned cnt = 0;
#pragma unroll
    for (int j = 0; j < 8; ++j) {
        if (lpos[j] < 0) {
            if (v2[j] > T0 + e0) cnt += (1u << 16);
            if (v2[j] > T1 + e1) cnt += 1u;
        }
    }
#pragma unroll
    for (int off = 16; off > 0; off >>= 1) cnt += __shfl_down_sync(0xffffffffu, cnt, off);
    if (lane == 0) s_warp[wid] = cnt;
    __syncthreads();
    if (tid == 0) {
        unsigned tot = 0;
        for (int w = 0; w < 8; ++w) tot += s_warp[w];
        int nIn0 = (int)(tot >> 16), nIn1 = (int)(tot & 0xFFFFu);
        int nd0 = 512 - nIn0, nd1 = 256 - nIn1;
        nd0 = nd0 < 0 ? 0 : (nd0 > nC ? nC : nd0);
        nd1 = nd1 < 0 ? 0 : (nd1 > nC ? nC : nd1);
        s_need[0] = nd0; s_need[1] = nd1;
    }
    __syncthreads();

    // exact rank within candidates (desc value, asc index)
    if (tid < nC) {
        const float mv = s_cv2[tid];
        const int   mi = s_cidx[tid];
        int rank = 0;
        for (int c = 0; c < nC; ++c)
            if (s_cv2[c] > mv || (s_cv2[c] == mv && s_cidx[c] < mi)) ++rank;
        s_csel[tid] = (rank < s_need[0] ? 1 : 0) | (rank < s_need[1] ? 2 : 0);
    }
    __syncthreads();

    // outputs
    const int* __restrict__ mrow = maskPrev + (size_t)row * HDIM_;
    float* __restrict__ nrow = maskNew + (size_t)row * HDIM_;
    __nv_bfloat16* __restrict__ hb0 = g_hb0 + (size_t)row * HDIM_;
    __nv_bfloat16* __restrict__ hb1 = g_hb1 + (size_t)row * HDIM_;

    int mp[8];
    *(int4*)&mp[0] = *(const int4*)&mrow[tid * 8];
    *(int4*)&mp[4] = *(const int4*)&mrow[tid * 8 + 4];

    __nv_bfloat16 b0[8], b1[8];
    float mn[8];
#pragma unroll
    for (int j = 0; j < 8; ++j) {
        bool share, cur;
        if (lpos[j] >= 0) {
            const int f = s_csel[lpos[j]];
            share = (f & 1) != 0;
            cur   = (f & 2) != 0;
        } else {
            share = v2[j] > T0 + e0;
            cur   = v2[j] > T1 + e1;
        }
        const float mv = share ? v[j] : 0.f;
        b0[j] = __float2bfloat16_rn(mv);
        b1[j] = __float2bfloat16_rn(mv - __bfloat162float(b0[j]));
        mn[j] = (float)mp[j] + (cur ? 1.f : 0.f);
    }
    *(uint4*)&hb0[tid * 8]       = *(uint4*)b0;
    *(uint4*)&hb1[tid * 8]       = *(uint4*)b1;
    *(float4*)&nrow[tid * 8]     = *(float4*)&mn[0];
    *(float4*)&nrow[tid * 8 + 4] = *(float4*)&mn[4];
}

extern "C" void kernel_launch(void* const* d_in, const int* in_sizes, int n_in,
                              void* d_out, int out_size)
{
    const float* x      = (const float*)d_in[0];
    const int*   mask_p = (const int*)  d_in[1];
    const float* W_enc  = (const float*)d_in[2];
    const float* b_enc  = (const float*)d_in[3];
    const float* W_dec  = (const float*)d_in[4];
    const float* b_dec  = (const float*)d_in[5];

    float* out      = (float*)d_out;
    float* mask_new = out + (size_t)M_TOT * ODIM_;

    float* hbuf;
    __nv_bfloat16 *hb0, *hb1, *xb0, *xb1, *we0, *we1, *wd0, *wd1;
    cudaGetSymbolAddress((void**)&hbuf, g_h);
    cudaGetSymbolAddress((void**)&hb0,  g_hb0);
    cudaGetSymbolAddress((void**)&hb1,  g_hb1);
    cudaGetSymbolAddress((void**)&xb0,  g_xb0);
    cudaGetSymbolAddress((void**)&xb1,  g_xb1);
    cudaGetSymbolAddress((void**)&we0,  g_we0);
    cudaGetSymbolAddress((void**)&we1,  g_we1);
    cudaGetSymbolAddress((void**)&wd0,  g_wd0);
    cudaGetSymbolAddress((void**)&wd1,  g_wd1);

    cudaFuncSetAttribute(gemm_bf3<true>,  cudaFuncAttributeMaxDynamicSharedMemorySize, SMEM_GG);
    cudaFuncSetAttribute(gemm_bf3<false>, cudaFuncAttributeMaxDynamicSharedMemorySize, SMEM_GG);

    // fused splits: 4096 blocks x, 512 W_enc, 512 W_dec
    split_all<<<5120, 256>>>(x, xb0, xb1, W_enc, we0, we1, W_dec, wd0, wd1);

    // encoder: h~ = x @ W_enc^T + b_enc, zero where mask_prev>0 (bf16 3-product)
    gemm_bf3<true ><<<PERSIST, 256, SMEM_GG>>>(
        xb0, xb1, we0, we1, b_enc, mask_p, hbuf, M_TOT, HDIM_, IDIM_);

    // exact dual top-k with band repair; emits mask_new + masked-h bf16 planes
    topk_band<<<M_TOT, 256>>>(mask_p, mask_new, x, W_enc, b_enc);

    // decoder: out = h_masked @ W_dec^T + b_dec
    gemm_bf3<false><<<PERSIST, 256, SMEM_GG>>>(
        hb0, hb1, wd0, wd1, b_dec, nullptr, out, M_TOT, ODIM_, HDIM_);
}

// round 14
// speedup vs baseline: 1.0394x; 1.0394x over previous
#include <cuda_runtime.h>
#include <cuda_bf16.h>
#include <stdint.h>

#define M_TOT 16384
#define HDIM_ 2048
#define IDIM_ 512
#define ODIM_ 512

// device-global scratch (no allocs allowed)
__device__ float         g_h  [(size_t)M_TOT * HDIM_];   // approx encoder output
__device__ __nv_bfloat16 g_hb0[(size_t)M_TOT * HDIM_];
__device__ __nv_bfloat16 g_hb1[(size_t)M_TOT * HDIM_];
__device__ __nv_bfloat16 g_xb0[(size_t)M_TOT * IDIM_];
__device__ __nv_bfloat16 g_xb1[(size_t)M_TOT * IDIM_];
__device__ __nv_bfloat16 g_we0[(size_t)HDIM_ * IDIM_];
__device__ __nv_bfloat16 g_we1[(size_t)HDIM_ * IDIM_];
__device__ __nv_bfloat16 g_wd0[(size_t)ODIM_ * HDIM_];
__device__ __nv_bfloat16 g_wd1[(size_t)ODIM_ * HDIM_];

__device__ __forceinline__ uint32_t smem_u32(const void* p){
    uint32_t a;
    asm("{ .reg .u64 t; cvta.to.shared.u64 t, %1; cvt.u32.u64 %0, t; }" : "=r"(a) : "l"(p));
    return a;
}
#define CP16(d, s) asm volatile("cp.async.cg.shared.global [%0], [%1], 16;" :: "r"(d), "l"(s))
#define CP_COMMIT() asm volatile("cp.async.commit_group;")
#define CP_WAIT0()  asm volatile("cp.async.wait_group 0;")

#define LDSM4(r, a) \
    asm volatile("ldmatrix.sync.aligned.m8n8.x4.shared.b16 {%0,%1,%2,%3}, [%4];" \
        : "=r"((r)[0]), "=r"((r)[1]), "=r"((r)[2]), "=r"((r)[3]) : "r"(a))

__device__ __forceinline__ void mma_bf16(float* c, const uint32_t* a, uint32_t b0, uint32_t b1){
    asm volatile("mma.sync.aligned.m16n8k16.row.col.f32.bf16.bf16.f32 "
        "{%0,%1,%2,%3},{%4,%5,%6,%7},{%8,%9},{%0,%1,%2,%3};"
        : "+f"(c[0]), "+f"(c[1]), "+f"(c[2]), "+f"(c[3])
        : "r"(a[0]), "r"(a[1]), "r"(a[2]), "r"(a[3]), "r"(b0), "r"(b1));
}

static constexpr int LDTH    = 40;            // halfs per smem row (32 + 8 pad)
static constexpr int PLANE_H = 128 * LDTH;
static constexpr int PLANE_B = PLANE_H * 2;
static constexpr int STAGE_B = 4 * PLANE_B;   // A0,A1,B0,B1 = 40960 B
static constexpr int BIAS_B  = 2 * STAGE_B;   // 2 stages (R12 structure)
static constexpr int SMEM_GG = BIAS_B + 512;  // 82432 B -> 2 CTAs/SM

// C[M,N] = (A0+A1)[M,K] * (B0+B1)[N,K]^T + bias[N]; 3-product bf16 mma.
// R12 mainloop: single __syncthreads per K-chunk, 2-stage, 2 CTAs/SM,
// classic (non-persistent) grid. mma order identical (bit-identical results).
template<bool EPI_MASK>
__global__ __launch_bounds__(256, 2)
void gemm_bf3(const __nv_bfloat16* __restrict__ A0, const __nv_bfloat16* __restrict__ A1,
              const __nv_bfloat16* __restrict__ B0, const __nv_bfloat16* __restrict__ B1,
              const float* __restrict__ bias, const int* __restrict__ maskPrev,
              float* __restrict__ C, int M, int N, int K)
{
    extern __shared__ char smem[];
    const uint32_t sb = smem_u32(smem);
    const int tid = threadIdx.x;
    const int lane = tid & 31, wid = tid >> 5;
    const int wm = wid & 3, wn = wid >> 2;        // 4 m-warps x 2 n-warps (32x64 warp tile)
    const int g = lane >> 2, t4 = lane & 3;
    const int m0 = blockIdx.y * 128, n0 = blockIdx.x * 128;

    float* sbias = (float*)(smem + BIAS_B);
    if (tid < 128) sbias[tid] = bias[n0 + tid];

    const int lr  = tid >> 1;
    const int lcb = (tid & 1) * 32;
    const __nv_bfloat16* pA0 = A0 + (size_t)(m0 + lr) * K;
    const __nv_bfloat16* pA1 = A1 + (size_t)(m0 + lr) * K;
    const __nv_bfloat16* pB0 = B0 + (size_t)(n0 + lr) * K;
    const __nv_bfloat16* pB1 = B1 + (size_t)(n0 + lr) * K;
    const uint32_t dof = (uint32_t)(lr * (LDTH * 2) + lcb);

    auto load_stage = [&](int kt, int s) {
        const uint32_t base = sb + (uint32_t)(s * STAGE_B) + dof;
        const int ko = kt * 32 + (lcb >> 1);
        CP16(base,               pA0 + ko); CP16(base + 16,               pA0 + ko + 8);
        CP16(base + PLANE_B,     pA1 + ko); CP16(base + PLANE_B + 16,     pA1 + ko + 8);
        CP16(base + 2 * PLANE_B, pB0 + ko); CP16(base + 2 * PLANE_B + 16, pB0 + ko + 8);
        CP16(base + 3 * PLANE_B, pB1 + ko); CP16(base + 3 * PLANE_B + 16, pB1 + ko + 8);
    };

    // ldmatrix lane address components
    const int a_r = ((lane >> 3) & 1) * 8 + (lane & 7);
    const int a_c = (lane >> 4) * 8;
    const int b_r = (lane >> 4) * 8 + (lane & 7);
    const int b_c = ((lane >> 3) & 1) * 8;
    uint32_t aoff[2][2], boff[2][4];
#pragma unroll
    for (int p = 0; p < 2; ++p) {
#pragma unroll
        for (int mt = 0; mt < 2; ++mt)
            aoff[p][mt] = (uint32_t)((p * PLANE_H + (wm * 32 + mt * 16 + a_r) * LDTH + a_c) * 2);
#pragma unroll
        for (int nt2 = 0; nt2 < 4; ++nt2)
            boff[p][nt2] = (uint32_t)(((2 + p) * PLANE_H + (wn * 64 + nt2 * 16 + b_r) * LDTH + b_c) * 2);
    }

    float acc[2][8][4];
#pragma unroll
    for (int a = 0; a < 2; ++a)
#pragma unroll
        for (int b = 0; b < 8; ++b)
#pragma unroll
            for (int q = 0; q < 4; ++q) acc[a][b][q] = 0.f;

    load_stage(0, 0); CP_COMMIT();

    const int KT = K >> 5;
    for (int kt = 0; kt < KT; ++kt) {
        const int s = kt & 1;
        CP_WAIT0();                 // stage-s loads (issued last iter) complete
        __syncthreads();            // publish stage s; all warps past previous compute
        if (kt + 1 < KT) load_stage(kt + 1, s ^ 1);
        CP_COMMIT();
        const uint32_t stu = sb + (uint32_t)(s * STAGE_B);
#pragma unroll
        for (int ks = 0; ks < 2; ++ks) {
            uint32_t af[2][2][4];
#pragma unroll
            for (int p = 0; p < 2; ++p)
#pragma unroll
                for (int mt = 0; mt < 2; ++mt)
                    LDSM4(af[p][mt], stu + aoff[p][mt] + ks * 32);
#pragma unroll
            for (int nt2 = 0; nt2 < 4; ++nt2) {
                uint32_t b0r[4], b1r[4];
                LDSM4(b0r, stu + boff[0][nt2] + ks * 32);
                LDSM4(b1r, stu + boff[1][nt2] + ks * 32);
#pragma unroll
                for (int h = 0; h < 2; ++h) {
                    const int nt = 2 * nt2 + h;
                    const uint32_t b00 = b0r[2 * h], b01 = b0r[2 * h + 1];
                    const uint32_t b10 = b1r[2 * h], b11 = b1r[2 * h + 1];
#pragma unroll
                    for (int mt = 0; mt < 2; ++mt) {
                        mma_bf16(acc[mt][nt], af[0][mt], b00, b01);  // a0*b0
                        mma_bf16(acc[mt][nt], af[0][mt], b10, b11);  // a0*b1
                        mma_bf16(acc[mt][nt], af[1][mt], b00, b01);  // a1*b0
                    }
                }
            }
        }
    }

#pragma unroll
    for (int mt = 0; mt < 2; ++mt) {
#pragma unroll
        for (int nt = 0; nt < 8; ++nt) {
            const int rr = m0 + wm * 32 + mt * 16 + g;
            const int cl = wn * 64 + nt * 8 + 2 * t4;
            const float b0 = sbias[cl];
            const float b1 = sbias[cl + 1];
            const float* c = acc[mt][nt];
            float2 v0 = make_float2(c[0] + b0, c[1] + b1);
            float2 v1 = make_float2(c[2] + b0, c[3] + b1);
            const size_t i0 = (size_t)rr * N + (n0 + cl);
            const size_t i1 = (size_t)(rr + 8) * N + (n0 + cl);
            if (EPI_MASK) {
                const int2 q0 = *(const int2*)(maskPrev + i0);
                const int2 q1 = *(const int2*)(maskPrev + i1);
                if (q0.x > 0) v0.x = 0.f;
                if (q0.y > 0) v0.y = 0.f;
                if (q1.x > 0) v1.x = 0.f;
                if (q1.y > 0) v1.y = 0.f;
            }
            *(float2*)(C + i0) = v0;
            *(float2*)(C + i1) = v1;
        }
    }
}

// fused fp32 -> 2-plane bf16 split for x, W_enc, W_dec in one launch
__global__ __launch_bounds__(256)
void split_all(const float* __restrict__ x,  __nv_bfloat16* __restrict__ xb0, __nv_bfloat16* __restrict__ xb1,
               const float* __restrict__ we, __nv_bfloat16* __restrict__ we0, __nv_bfloat16* __restrict__ we1,
               const float* __restrict__ wd, __nv_bfloat16* __restrict__ wd0, __nv_bfloat16* __restrict__ wd1)
{
    const int b = blockIdx.x;
    const float* src;
    __nv_bfloat16 *p0, *p1;
    int i;
    if (b < 4096)      { src = x;  p0 = xb0; p1 = xb1; i = b * 256 + threadIdx.x; }
    else if (b < 4608) { src = we; p0 = we0; p1 = we1; i = (b - 4096) * 256 + threadIdx.x; }
    else               { src = wd; p0 = wd0; p1 = wd1; i = (b - 4608) * 256 + threadIdx.x; }
    float4 v0 = ((const float4*)src)[2 * i];
    float4 v1 = ((const float4*)src)[2 * i + 1];
    float xv[8] = {v0.x, v0.y, v0.z, v0.w, v1.x, v1.y, v1.z, v1.w};
    __nv_bfloat16 b0[8], b1[8];
#pragma unroll
    for (int j = 0; j < 8; ++j) {
        b0[j] = __float2bfloat16_rn(xv[j]);
        b1[j] = __float2bfloat16_rn(xv[j] - __bfloat162float(b0[j]));
    }
    ((uint4*)p0)[i] = *(uint4*)b0;
    ((uint4*)p1)[i] = *(uint4*)b1;
}

// ---------------------------------------------------------------------------
// Dual top-k (512/256) over approx h^2 with epsilon-band exact repair.
// Joint radix on the top 24 bits (3 passes). Histogram regions are disjoint
// per pass and pre-zeroed once, removing the zero+sync pair inside each pass
// (thresholds integer-identical to R12).
// ---------------------------------------------------------------------------
static constexpr int CAP = 64;

__global__ __launch_bounds__(256)
void topk_band(const int* __restrict__ maskPrev, float* __restrict__ maskNew,
               const float* __restrict__ x, const float* __restrict__ W_enc,
               const float* __restrict__ b_enc)
{
    __shared__ unsigned s_hist[1280];    // pass0:[0,256) pass1:[256,768) pass2:[768,1280)
    __shared__ unsigned s_warp[8];
    __shared__ unsigned s_wsuf[8];
    __shared__ unsigned s_pick0[2];
    __shared__ unsigned s_pick1[2];
    __shared__ float    s_x[IDIM_];
    __shared__ int      s_cidx[CAP];
    __shared__ float    s_cv2[CAP];
    __shared__ int      s_csel[CAP];
    __shared__ int      s_ccnt;
    __shared__ int      s_need[2];

    const int row = blockIdx.x, tid = threadIdx.x;
    const int lane = tid & 31, wid = tid >> 5;
    const float* __restrict__ hrow = g_h + (size_t)row * HDIM_;

    float v[8], v2[8]; unsigned u[8];
    *(float4*)&v[0] = *(const float4*)&hrow[tid * 8];
    *(float4*)&v[4] = *(const float4*)&hrow[tid * 8 + 4];
#pragma unroll
    for (int j = 0; j < 8; ++j) { v2[j] = v[j] * v[j]; u[j] = __float_as_uint(v2[j]); }

    s_x[tid]       = x[(size_t)row * IDIM_ + tid];
    s_x[tid + 256] = x[(size_t)row * IDIM_ + tid + 256];
    if (tid == 0) s_ccnt = 0;

    // pre-zero ALL histogram regions once
    s_hist[tid] = 0u; s_hist[tid + 256] = 0u; s_hist[tid + 512] = 0u;
    s_hist[tid + 768] = 0u; s_hist[tid + 1024] = 0u;
    __syncthreads();

    unsigned prefix0, prefix1, kk0, kk1, pmask;

    // ---- pass 0 (shared histogram, top byte), joint pick for k=512 and k=256
#pragma unroll
    for (int j = 0; j < 8; ++j) atomicAdd(&s_hist[u[j] >> 24], 1u);
    __syncthreads();
    {
        const unsigned cnt = s_hist[tid];
        unsigned suf = cnt;
#pragma unroll
        for (int off = 1; off < 32; off <<= 1) {
            unsigned t = __shfl_down_sync(0xffffffffu, suf, off);
            if (lane + off < 32) suf += t;
        }
        const unsigned wtot = __shfl_sync(0xffffffffu, suf, 0);
        if (lane == 0) s_warp[wid] = wtot;
        __syncthreads();
        if (tid < 8) {
            unsigned s = 0;
            for (int w = tid + 1; w < 8; ++w) s += s_warp[w];
            s_wsuf[tid] = s;
        }
        __syncthreads();
        suf += s_wsuf[wid];
        if (suf >= 512u && suf - cnt < 512u) { s_pick0[0] = (unsigned)tid; s_pick0[1] = 512u - (suf - cnt); }
        if (suf >= 256u && suf - cnt < 256u) { s_pick1[0] = (unsigned)tid; s_pick1[1] = 256u - (suf - cnt); }
        __syncthreads();
        prefix0 = s_pick0[0] << 24; kk0 = s_pick0[1];
        prefix1 = s_pick1[0] << 24; kk1 = s_pick1[1];
        pmask = 255u << 24;
    }

    // ---- passes 1..2: joint dual histograms (pre-zeroed disjoint regions)
#pragma unroll 1
    for (int pass = 1; pass < 3; ++pass) {
        const int shift = 24 - 8 * pass;
        const int base = 256 + (pass - 1) * 512;   // region start for this pass
#pragma unroll
        for (int j = 0; j < 8; ++j) {
            if ((u[j] & pmask) == prefix0) atomicAdd(&s_hist[base + ((u[j] >> shift) & 255u)], 1u);
            if ((u[j] & pmask) == prefix1) atomicAdd(&s_hist[base + 256 + ((u[j] >> shift) & 255u)], 1u);
        }
        __syncthreads();
        const unsigned cnt0 = s_hist[base + tid], cnt1 = s_hist[base + 256 + tid];
        unsigned suf = (cnt0 << 16) | cnt1;
#pragma unroll
        for (int off = 1; off < 32; off <<= 1) {
            unsigned t = __shfl_down_sync(0xffffffffu, suf, off);
            if (lane + off < 32) suf += t;
        }
        const unsigned wtot = __shfl_sync(0xffffffffu, suf, 0);
        if (lane == 0) s_warp[wid] = wtot;
        __syncthreads();
        if (tid < 8) {
            unsigned s = 0;
            for (int w = tid + 1; w < 8; ++w) s += s_warp[w];
            s_wsuf[tid] = s;
        }
        __syncthreads();
        suf += s_wsuf[wid];
        const unsigned suf0 = suf >> 16, suf1 = suf & 0xFFFFu;
        if (suf0 >= kk0 && suf0 - cnt0 < kk0) { s_pick0[0] = (unsigned)tid; s_pick0[1] = kk0 - (suf0 - cnt0); }
        if (suf1 >= kk1 && suf1 - cnt1 < kk1) { s_pick1[0] = (unsigned)tid; s_pick1[1] = kk1 - (suf1 - cnt1); }
        __syncthreads();
        prefix0 |= s_pick0[0] << shift; kk0 = s_pick0[1];
        prefix1 |= s_pick1[0] << shift; kk1 = s_pick1[1];
        pmask  |= 255u << shift;
    }
    __syncthreads();

    // T truncated to top-24 bits: T_hat <= T_true, relative gap <= 2^-16.
    const float T0 = __uint_as_float(prefix0), T1 = __uint_as_float(prefix1);
    const float e0 = T0 * 1e-3f, e1 = T1 * 1e-3f;

    // collect band candidates
    int lpos[8];
#pragma unroll
    for (int j = 0; j < 8; ++j) {
        lpos[j] = -1;
        const bool cand = (fabsf(v2[j] - T0) <= e0) || (fabsf(v2[j] - T1) <= e1);
        if (cand) {
            int p = atomicAdd(&s_ccnt, 1);
            if (p < CAP) { s_cidx[p] = tid * 8 + j; lpos[j] = p; }
        }
    }
    __syncthreads();
    const int nC = min(s_ccnt, CAP);

    // exact recompute of candidates (one warp per candidate, round-robin)
    for (int c = wid; c < nC; c += 8) {
        const int ch = s_cidx[c];
        const float* wr = W_enc + (size_t)ch * IDIM_;
        float s = 0.f;
#pragma unroll 4
        for (int k2 = lane; k2 < IDIM_; k2 += 32) s = fmaf(s_x[k2], wr[k2], s);
#pragma unroll
        for (int off = 16; off > 0; off >>= 1) s += __shfl_down_sync(0xffffffffu, s, off);
        if (lane == 0) {
            float hex = s + b_enc[ch];
            if (maskPrev[(size_t)row * HDIM_ + ch] > 0) hex = 0.f;
            s_cv2[c] = hex * hex;
        }
    }
    __syncthreads();

    // count definite-ins among non-candidates (packed 16|16)
    unsigned cnt = 0;
#pragma unroll
    for (int j = 0; j < 8; ++j) {
        if (lpos[j] < 0) {
            if (v2[j] > T0 + e0) cnt += (1u << 16);
            if (v2[j] > T1 + e1) cnt += 1u;
        }
    }
#pragma unroll
    for (int off = 16; off > 0; off >>= 1) cnt += __shfl_down_sync(0xffffffffu, cnt, off);
    if (lane == 0) s_warp[wid] = cnt;
    __syncthreads();
    if (tid == 0) {
        unsigned tot = 0;
        for (int w = 0; w < 8; ++w) tot += s_warp[w];
        int nIn0 = (int)(tot >> 16), nIn1 = (int)(tot & 0xFFFFu);
        int nd0 = 512 - nIn0, nd1 = 256 - nIn1;
        nd0 = nd0 < 0 ? 0 : (nd0 > nC ? nC : nd0);
        nd1 = nd1 < 0 ? 0 : (nd1 > nC ? nC : nd1);
        s_need[0] = nd0; s_need[1] = nd1;
    }
    __syncthreads();

    // exact rank within candidates (desc value, asc index)
    if (tid < nC) {
        const float mv = s_cv2[tid];
        const int   mi = s_cidx[tid];
        int rank = 0;
        for (int c = 0; c < nC; ++c)
            if (s_cv2[c] > mv || (s_cv2[c] == mv && s_cidx[c] < mi)) ++rank;
        s_csel[tid] = (rank < s_need[0] ? 1 : 0) | (rank < s_need[1] ? 2 : 0);
    }
    __syncthreads();

    // outputs
    const int* __restrict__ mrow = maskPrev + (size_t)row * HDIM_;
    float* __restrict__ nrow = maskNew + (size_t)row * HDIM_;
    __nv_bfloat16* __restrict__ hb0 = g_hb0 + (size_t)row * HDIM_;
    __nv_bfloat16* __restrict__ hb1 = g_hb1 + (size_t)row * HDIM_;

    int mp[8];
    *(int4*)&mp[0] = *(const int4*)&mrow[tid * 8];
    *(int4*)&mp[4] = *(const int4*)&mrow[tid * 8 + 4];

    __nv_bfloat16 b0[8], b1[8];
    float mn[8];
#pragma unroll
    for (int j = 0; j < 8; ++j) {
        bool share, cur;
        if (lpos[j] >= 0) {
            const int f = s_csel[lpos[j]];
            share = (f & 1) != 0;
            cur   = (f & 2) != 0;
        } else {
            share = v2[j] > T0 + e0;
            cur   = v2[j] > T1 + e1;
        }
        const float mv = share ? v[j] : 0.f;
        b0[j] = __float2bfloat16_rn(mv);
        b1[j] = __float2bfloat16_rn(mv - __bfloat162float(b0[j]));
        mn[j] = (float)mp[j] + (cur ? 1.f : 0.f);
    }
    *(uint4*)&hb0[tid * 8]       = *(uint4*)b0;
    *(uint4*)&hb1[tid * 8]       = *(uint4*)b1;
    *(float4*)&nrow[tid * 8]     = *(float4*)&mn[0];
    *(float4*)&nrow[tid * 8 + 4] = *(float4*)&mn[4];
}

extern "C" void kernel_launch(void* const* d_in, const int* in_sizes, int n_in,
                              void* d_out, int out_size)
{
    const float* x      = (const float*)d_in[0];
    const int*   mask_p = (const int*)  d_in[1];
    const float* W_enc  = (const float*)d_in[2];
    const float* b_enc  = (const float*)d_in[3];
    const float* W_dec  = (const float*)d_in[4];
    const float* b_dec  = (const float*)d_in[5];

    float* out      = (float*)d_out;
    float* mask_new = out + (size_t)M_TOT * ODIM_;

    float* hbuf;
    __nv_bfloat16 *hb0, *hb1, *xb0, *xb1, *we0, *we1, *wd0, *wd1;
    cudaGetSymbolAddress((void**)&hbuf, g_h);
    cudaGetSymbolAddress((void**)&hb0,  g_hb0);
    cudaGetSymbolAddress((void**)&hb1,  g_hb1);
    cudaGetSymbolAddress((void**)&xb0,  g_xb0);
    cudaGetSymbolAddress((void**)&xb1,  g_xb1);
    cudaGetSymbolAddress((void**)&we0,  g_we0);
    cudaGetSymbolAddress((void**)&we1,  g_we1);
    cudaGetSymbolAddress((void**)&wd0,  g_wd0);
    cudaGetSymbolAddress((void**)&wd1,  g_wd1);

    cudaFuncSetAttribute(gemm_bf3<true>,  cudaFuncAttributeMaxDynamicSharedMemorySize, SMEM_GG);
    cudaFuncSetAttribute(gemm_bf3<false>, cudaFuncAttributeMaxDynamicSharedMemorySize, SMEM_GG);

    // fused splits: 4096 blocks x, 512 W_enc, 512 W_dec
    split_all<<<5120, 256>>>(x, xb0, xb1, W_enc, we0, we1, W_dec, wd0, wd1);

    // encoder: h~ = x @ W_enc^T + b_enc, zero where mask_prev>0 (bf16 3-product)
    gemm_bf3<true ><<<dim3(HDIM_ / 128, M_TOT / 128), 256, SMEM_GG>>>(
        xb0, xb1, we0, we1, b_enc, mask_p, hbuf, M_TOT, HDIM_, IDIM_);

    // exact dual top-k with band repair; emits mask_new + masked-h bf16 planes
    topk_band<<<M_TOT, 256>>>(mask_p, mask_new, x, W_enc, b_enc);

    // decoder: out = h_masked @ W_dec^T + b_dec
    gemm_bf3<false><<<dim3(ODIM_ / 128, M_TOT / 128), 256, SMEM_GG>>>(
        hb0, hb1, wd0, wd1, b_dec, nullptr, out, M_TOT, ODIM_, HDIM_);
}

// round 15
// speedup vs baseline: 1.1032x; 1.0613x over previous
#include <cuda_runtime.h>
#include <cuda_bf16.h>
#include <stdint.h>

#define M_TOT 16384
#define HDIM_ 2048
#define IDIM_ 512
#define ODIM_ 512

// device-global scratch (no allocs allowed)
__device__ float         g_h  [(size_t)M_TOT * HDIM_];   // approx encoder output
__device__ __nv_bfloat16 g_hb0[(size_t)M_TOT * HDIM_];
__device__ __nv_bfloat16 g_hb1[(size_t)M_TOT * HDIM_];
__device__ __nv_bfloat16 g_xb0[(size_t)M_TOT * IDIM_];
__device__ __nv_bfloat16 g_xb1[(size_t)M_TOT * IDIM_];
__device__ __nv_bfloat16 g_we0[(size_t)HDIM_ * IDIM_];
__device__ __nv_bfloat16 g_we1[(size_t)HDIM_ * IDIM_];
__device__ __nv_bfloat16 g_wd0[(size_t)ODIM_ * HDIM_];
__device__ __nv_bfloat16 g_wd1[(size_t)ODIM_ * HDIM_];

__device__ __forceinline__ uint32_t smem_u32(const void* p){
    uint32_t a;
    asm("{ .reg .u64 t; cvta.to.shared.u64 t, %1; cvt.u32.u64 %0, t; }" : "=r"(a) : "l"(p));
    return a;
}
#define CP16(d, s) asm volatile("cp.async.cg.shared.global [%0], [%1], 16;" :: "r"(d), "l"(s))
#define CP_COMMIT() asm volatile("cp.async.commit_group;")
#define CP_WAIT0()  asm volatile("cp.async.wait_group 0;")

#define LDSM4(r, a) \
    asm volatile("ldmatrix.sync.aligned.m8n8.x4.shared.b16 {%0,%1,%2,%3}, [%4];" \
        : "=r"((r)[0]), "=r"((r)[1]), "=r"((r)[2]), "=r"((r)[3]) : "r"(a))

__device__ __forceinline__ void mma_bf16(float* c, const uint32_t* a, uint32_t b0, uint32_t b1){
    asm volatile("mma.sync.aligned.m16n8k16.row.col.f32.bf16.bf16.f32 "
        "{%0,%1,%2,%3},{%4,%5,%6,%7},{%8,%9},{%0,%1,%2,%3};"
        : "+f"(c[0]), "+f"(c[1]), "+f"(c[2]), "+f"(c[3])
        : "r"(a[0]), "r"(a[1]), "r"(a[2]), "r"(a[3]), "r"(b0), "r"(b1));
}

static constexpr int LDTH    = 40;            // halfs per smem row (32 + 8 pad)
static constexpr int PLANE_H = 128 * LDTH;
static constexpr int PLANE_B = PLANE_H * 2;
static constexpr int STAGE_B = 4 * PLANE_B;   // A0,A1,B0,B1 = 40960 B
static constexpr int BIAS_B  = 2 * STAGE_B;   // 2 stages
static constexpr int SMEM_GG = BIAS_B + 512;  // 82432 B -> 2 CTAs/SM

// C[M,N] = (A0+A1)[M,K] * (B0+B1)[N,K]^T + bias[N]; 3-product bf16 mma.
// Chunk body restructured for dependency density: per ks, ALL 12 LDSM issued
// up front, cp.async prefetch overlapped with ks0 fragment latency, then the
// 96 mma run dense. Per-accumulator mma order identical to R8-R14
// (bit-identical results).
template<bool EPI_MASK>
__global__ __launch_bounds__(256, 2)
void gemm_bf3(const __nv_bfloat16* __restrict__ A0, const __nv_bfloat16* __restrict__ A1,
              const __nv_bfloat16* __restrict__ B0, const __nv_bfloat16* __restrict__ B1,
              const float* __restrict__ bias, const int* __restrict__ maskPrev,
              float* __restrict__ C, int M, int N, int K)
{
    extern __shared__ char smem[];
    const uint32_t sb = smem_u32(smem);
    const int tid = threadIdx.x;
    const int lane = tid & 31, wid = tid >> 5;
    const int wm = wid & 3, wn = wid >> 2;        // 4 m-warps x 2 n-warps (32x64 warp tile)
    const int g = lane >> 2, t4 = lane & 3;
    const int m0 = blockIdx.y * 128, n0 = blockIdx.x * 128;

    float* sbias = (float*)(smem + BIAS_B);
    if (tid < 128) sbias[tid] = bias[n0 + tid];

    const int lr  = tid >> 1;
    const int lcb = (tid & 1) * 32;
    const __nv_bfloat16* pA0 = A0 + (size_t)(m0 + lr) * K;
    const __nv_bfloat16* pA1 = A1 + (size_t)(m0 + lr) * K;
    const __nv_bfloat16* pB0 = B0 + (size_t)(n0 + lr) * K;
    const __nv_bfloat16* pB1 = B1 + (size_t)(n0 + lr) * K;
    const uint32_t dof = (uint32_t)(lr * (LDTH * 2) + lcb);

    auto load_stage = [&](int kt, int s) {
        const uint32_t base = sb + (uint32_t)(s * STAGE_B) + dof;
        const int ko = kt * 32 + (lcb >> 1);
        CP16(base,               pA0 + ko); CP16(base + 16,               pA0 + ko + 8);
        CP16(base + PLANE_B,     pA1 + ko); CP16(base + PLANE_B + 16,     pA1 + ko + 8);
        CP16(base + 2 * PLANE_B, pB0 + ko); CP16(base + 2 * PLANE_B + 16, pB0 + ko + 8);
        CP16(base + 3 * PLANE_B, pB1 + ko); CP16(base + 3 * PLANE_B + 16, pB1 + ko + 8);
    };

    // ldmatrix lane address components
    const int a_r = ((lane >> 3) & 1) * 8 + (lane & 7);
    const int a_c = (lane >> 4) * 8;
    const int b_r = (lane >> 4) * 8 + (lane & 7);
    const int b_c = ((lane >> 3) & 1) * 8;
    uint32_t aoff[2][2], boff[2][4];
#pragma unroll
    for (int p = 0; p < 2; ++p) {
#pragma unroll
        for (int mt = 0; mt < 2; ++mt)
            aoff[p][mt] = (uint32_t)((p * PLANE_H + (wm * 32 + mt * 16 + a_r) * LDTH + a_c) * 2);
#pragma unroll
        for (int nt2 = 0; nt2 < 4; ++nt2)
            boff[p][nt2] = (uint32_t)(((2 + p) * PLANE_H + (wn * 64 + nt2 * 16 + b_r) * LDTH + b_c) * 2);
    }

    float acc[2][8][4];
#pragma unroll
    for (int a = 0; a < 2; ++a)
#pragma unroll
        for (int b = 0; b < 8; ++b)
#pragma unroll
            for (int q = 0; q < 4; ++q) acc[a][b][q] = 0.f;

    load_stage(0, 0); CP_COMMIT();

    const int KT = K >> 5;
    for (int kt = 0; kt < KT; ++kt) {
        const int s = kt & 1;
        CP_WAIT0();                 // stage-s loads (issued last iter) complete
        __syncthreads();            // publish stage s; all warps past previous compute
        const uint32_t stu = sb + (uint32_t)(s * STAGE_B);
        const bool pre = (kt + 1 < KT);
#pragma unroll
        for (int ks = 0; ks < 2; ++ks) {
            // --- issue ALL fragment loads for this ks up front ---
            uint32_t af[2][2][4];   // [plane][mt]
            uint32_t bf[8][4];      // [2*nt2 + plane]
#pragma unroll
            for (int p = 0; p < 2; ++p)
#pragma unroll
                for (int mt = 0; mt < 2; ++mt)
                    LDSM4(af[p][mt], stu + aoff[p][mt] + ks * 32);
#pragma unroll
            for (int nt2 = 0; nt2 < 4; ++nt2) {
                LDSM4(bf[2 * nt2 + 0], stu + boff[0][nt2] + ks * 32);
                LDSM4(bf[2 * nt2 + 1], stu + boff[1][nt2] + ks * 32);
            }
            // overlap next-stage cp.async with ks0 fragment latency
            if (ks == 0) {
                if (pre) load_stage(kt + 1, s ^ 1);
                CP_COMMIT();
            }
            // --- dense mma block (per-accumulator order unchanged) ---
#pragma unroll
            for (int nt2 = 0; nt2 < 4; ++nt2) {
#pragma unroll
                for (int h = 0; h < 2; ++h) {
                    const int nt = 2 * nt2 + h;
                    const uint32_t b00 = bf[2 * nt2 + 0][2 * h], b01 = bf[2 * nt2 + 0][2 * h + 1];
                    const uint32_t b10 = bf[2 * nt2 + 1][2 * h], b11 = bf[2 * nt2 + 1][2 * h + 1];
#pragma unroll
                    for (int mt = 0; mt < 2; ++mt) {
                        mma_bf16(acc[mt][nt], af[0][mt], b00, b01);  // a0*b0
                        mma_bf16(acc[mt][nt], af[0][mt], b10, b11);  // a0*b1
                        mma_bf16(acc[mt][nt], af[1][mt], b00, b01);  // a1*b0
                    }
                }
            }
        }
    }

#pragma unroll
    for (int mt = 0; mt < 2; ++mt) {
#pragma unroll
        for (int nt = 0; nt < 8; ++nt) {
            const int rr = m0 + wm * 32 + mt * 16 + g;
            const int cl = wn * 64 + nt * 8 + 2 * t4;
            const float b0 = sbias[cl];
            const float b1 = sbias[cl + 1];
            const float* c = acc[mt][nt];
            float2 v0 = make_float2(c[0] + b0, c[1] + b1);
            float2 v1 = make_float2(c[2] + b0, c[3] + b1);
            const size_t i0 = (size_t)rr * N + (n0 + cl);
            const size_t i1 = (size_t)(rr + 8) * N + (n0 + cl);
            if (EPI_MASK) {
                const int2 q0 = *(const int2*)(maskPrev + i0);
                const int2 q1 = *(const int2*)(maskPrev + i1);
                if (q0.x > 0) v0.x = 0.f;
                if (q0.y > 0) v0.y = 0.f;
                if (q1.x > 0) v1.x = 0.f;
                if (q1.y > 0) v1.y = 0.f;
            }
            *(float2*)(C + i0) = v0;
            *(float2*)(C + i1) = v1;
        }
    }
}

// fused fp32 -> 2-plane bf16 split for x, W_enc, W_dec in one launch
__global__ __launch_bounds__(256)
void split_all(const float* __restrict__ x,  __nv_bfloat16* __restrict__ xb0, __nv_bfloat16* __restrict__ xb1,
               const float* __restrict__ we, __nv_bfloat16* __restrict__ we0, __nv_bfloat16* __restrict__ we1,
               const float* __restrict__ wd, __nv_bfloat16* __restrict__ wd0, __nv_bfloat16* __restrict__ wd1)
{
    const int b = blockIdx.x;
    const float* src;
    __nv_bfloat16 *p0, *p1;
    int i;
    if (b < 4096)      { src = x;  p0 = xb0; p1 = xb1; i = b * 256 + threadIdx.x; }
    else if (b < 4608) { src = we; p0 = we0; p1 = we1; i = (b - 4096) * 256 + threadIdx.x; }
    else               { src = wd; p0 = wd0; p1 = wd1; i = (b - 4608) * 256 + threadIdx.x; }
    float4 v0 = ((const float4*)src)[2 * i];
    float4 v1 = ((const float4*)src)[2 * i + 1];
    float xv[8] = {v0.x, v0.y, v0.z, v0.w, v1.x, v1.y, v1.z, v1.w};
    __nv_bfloat16 b0[8], b1[8];
#pragma unroll
    for (int j = 0; j < 8; ++j) {
        b0[j] = __float2bfloat16_rn(xv[j]);
        b1[j] = __float2bfloat16_rn(xv[j] - __bfloat162float(b0[j]));
    }
    ((uint4*)p0)[i] = *(uint4*)b0;
    ((uint4*)p1)[i] = *(uint4*)b1;
}

// ---------------------------------------------------------------------------
// Dual top-k (512/256) over approx h^2 with epsilon-band exact repair.
// Joint radix on the top 24 bits (3 passes); pre-zeroed disjoint histogram
// regions. Thresholds integer-identical to R12.
// ---------------------------------------------------------------------------
static constexpr int CAP = 64;

__global__ __launch_bounds__(256)
void topk_band(const int* __restrict__ maskPrev, float* __restrict__ maskNew,
               const float* __restrict__ x, const float* __restrict__ W_enc,
               const float* __restrict__ b_enc)
{
    __shared__ unsigned s_hist[1280];    // pass0:[0,256) pass1:[256,768) pass2:[768,1280)
    __shared__ unsigned s_warp[8];
    __shared__ unsigned s_wsuf[8];
    __shared__ unsigned s_pick0[2];
    __shared__ unsigned s_pick1[2];
    __shared__ float    s_x[IDIM_];
    __shared__ int      s_cidx[CAP];
    __shared__ float    s_cv2[CAP];
    __shared__ int      s_csel[CAP];
    __shared__ int      s_ccnt;
    __shared__ int      s_need[2];

    const int row = blockIdx.x, tid = threadIdx.x;
    const int lane = tid & 31, wid = tid >> 5;
    const float* __restrict__ hrow = g_h + (size_t)row * HDIM_;

    float v[8], v2[8]; unsigned u[8];
    *(float4*)&v[0] = *(const float4*)&hrow[tid * 8];
    *(float4*)&v[4] = *(const float4*)&hrow[tid * 8 + 4];
#pragma unroll
    for (int j = 0; j < 8; ++j) { v2[j] = v[j] * v[j]; u[j] = __float_as_uint(v2[j]); }

    s_x[tid]       = x[(size_t)row * IDIM_ + tid];
    s_x[tid + 256] = x[(size_t)row * IDIM_ + tid + 256];
    if (tid == 0) s_ccnt = 0;

    // pre-zero ALL histogram regions once
    s_hist[tid] = 0u; s_hist[tid + 256] = 0u; s_hist[tid + 512] = 0u;
    s_hist[tid + 768] = 0u; s_hist[tid + 1024] = 0u;
    __syncthreads();

    unsigned prefix0, prefix1, kk0, kk1, pmask;

    // ---- pass 0 (shared histogram, top byte), joint pick for k=512 and k=256
#pragma unroll
    for (int j = 0; j < 8; ++j) atomicAdd(&s_hist[u[j] >> 24], 1u);
    __syncthreads();
    {
        const unsigned cnt = s_hist[tid];
        unsigned suf = cnt;
#pragma unroll
        for (int off = 1; off < 32; off <<= 1) {
            unsigned t = __shfl_down_sync(0xffffffffu, suf, off);
            if (lane + off < 32) suf += t;
        }
        const unsigned wtot = __shfl_sync(0xffffffffu, suf, 0);
        if (lane == 0) s_warp[wid] = wtot;
        __syncthreads();
        if (tid < 8) {
            unsigned s = 0;
            for (int w = tid + 1; w < 8; ++w) s += s_warp[w];
            s_wsuf[tid] = s;
        }
        __syncthreads();
        suf += s_wsuf[wid];
        if (suf >= 512u && suf - cnt < 512u) { s_pick0[0] = (unsigned)tid; s_pick0[1] = 512u - (suf - cnt); }
        if (suf >= 256u && suf - cnt < 256u) { s_pick1[0] = (unsigned)tid; s_pick1[1] = 256u - (suf - cnt); }
        __syncthreads();
        prefix0 = s_pick0[0] << 24; kk0 = s_pick0[1];
        prefix1 = s_pick1[0] << 24; kk1 = s_pick1[1];
        pmask = 255u << 24;
    }

    // ---- passes 1..2: joint dual histograms (pre-zeroed disjoint regions)
#pragma unroll 1
    for (int pass = 1; pass < 3; ++pass) {
        const int shift = 24 - 8 * pass;
        const int base = 256 + (pass - 1) * 512;
#pragma unroll
        for (int j = 0; j < 8; ++j) {
            if ((u[j] & pmask) == prefix0) atomicAdd(&s_hist[base + ((u[j] >> shift) & 255u)], 1u);
            if ((u[j] & pmask) == prefix1) atomicAdd(&s_hist[base + 256 + ((u[j] >> shift) & 255u)], 1u);
        }
        __syncthreads();
        const unsigned cnt0 = s_hist[base + tid], cnt1 = s_hist[base + 256 + tid];
        unsigned suf = (cnt0 << 16) | cnt1;
#pragma unroll
        for (int off = 1; off < 32; off <<= 1) {
            unsigned t = __shfl_down_sync(0xffffffffu, suf, off);
            if (lane + off < 32) suf += t;
        }
        const unsigned wtot = __shfl_sync(0xffffffffu, suf, 0);
        if (lane == 0) s_warp[wid] = wtot;
        __syncthreads();
        if (tid < 8) {
            unsigned s = 0;
            for (int w = tid + 1; w < 8; ++w) s += s_warp[w];
            s_wsuf[tid] = s;
        }
        __syncthreads();
        suf += s_wsuf[wid];
        const unsigned suf0 = suf >> 16, suf1 = suf & 0xFFFFu;
        if (suf0 >= kk0 && suf0 - cnt0 < kk0) { s_pick0[0] = (unsigned)tid; s_pick0[1] = kk0 - (suf0 - cnt0); }
        if (suf1 >= kk1 && suf1 - cnt1 < kk1) { s_pick1[0] = (unsigned)tid; s_pick1[1] = kk1 - (suf1 - cnt1); }
        __syncthreads();
        prefix0 |= s_pick0[0] << shift; kk0 = s_pick0[1];
        prefix1 |= s_pick1[0] << shift; kk1 = s_pick1[1];
        pmask  |= 255u << shift;
    }
    __syncthreads();

    // T truncated to top-24 bits: T_hat <= T_true, relative gap <= 2^-16.
    const float T0 = __uint_as_float(prefix0), T1 = __uint_as_float(prefix1);
    const float e0 = T0 * 1e-3f, e1 = T1 * 1e-3f;

    // collect band candidates
    int lpos[8];
#pragma unroll
    for (int j = 0; j < 8; ++j) {
        lpos[j] = -1;
        const bool cand = (fabsf(v2[j] - T0) <= e0) || (fabsf(v2[j] - T1) <= e1);
        if (cand) {
            int p = atomicAdd(&s_ccnt, 1);
            if (p < CAP) { s_cidx[p] = tid * 8 + j; lpos[j] = p; }
        }
    }
    __syncthreads();
    const int nC = min(s_ccnt, CAP);

    // exact recompute of candidates (one warp per candidate, round-robin)
    for (int c = wid; c < nC; c += 8) {
        const int ch = s_cidx[c];
        const float* wr = W_enc + (size_t)ch * IDIM_;
        float s = 0.f;
#pragma unroll 4
        for (int k2 = lane; k2 < IDIM_; k2 += 32) s = fmaf(s_x[k2], wr[k2], s);
#pragma unroll
        for (int off = 16; off > 0; off >>= 1) s += __shfl_down_sync(0xffffffffu, s, off);
        if (lane == 0) {
            float hex = s + b_enc[ch];
            if (maskPrev[(size_t)row * HDIM_ + ch] > 0) hex = 0.f;
            s_cv2[c] = hex * hex;
        }
    }
    __syncthreads();

    // count definite-ins among non-candidates (packed 16|16)
    unsigned cnt = 0;
#pragma unroll
    for (int j = 0; j < 8; ++j) {
        if (lpos[j] < 0) {
            if (v2[j] > T0 + e0) cnt += (1u << 16);
            if (v2[j] > T1 + e1) cnt += 1u;
        }
    }
#pragma unroll
    for (int off = 16; off > 0; off >>= 1) cnt += __shfl_down_sync(0xffffffffu, cnt, off);
    if (lane == 0) s_warp[wid] = cnt;
    __syncthreads();
    if (tid == 0) {
        unsigned tot = 0;
        for (int w = 0; w < 8; ++w) tot += s_warp[w];
        int nIn0 = (int)(tot >> 16), nIn1 = (int)(tot & 0xFFFFu);
        int nd0 = 512 - nIn0, nd1 = 256 - nIn1;
        nd0 = nd0 < 0 ? 0 : (nd0 > nC ? nC : nd0);
        nd1 = nd1 < 0 ? 0 : (nd1 > nC ? nC : nd1);
        s_need[0] = nd0; s_need[1] = nd1;
    }
    __syncthreads();

    // exact rank within candidates (desc value, asc index)
    if (tid < nC) {
        const float mv = s_cv2[tid];
        const int   mi = s_cidx[tid];
        int rank = 0;
        for (int c = 0; c < nC; ++c)
            if (s_cv2[c] > mv || (s_cv2[c] == mv && s_cidx[c] < mi)) ++rank;
        s_csel[tid] = (rank < s_need[0] ? 1 : 0) | (rank < s_need[1] ? 2 : 0);
    }
    __syncthreads();

    // outputs
    const int* __restrict__ mrow = maskPrev + (size_t)row * HDIM_;
    float* __restrict__ nrow = maskNew + (size_t)row * HDIM_;
    __nv_bfloat16* __restrict__ hb0 = g_hb0 + (size_t)row * HDIM_;
    __nv_bfloat16* __restrict__ hb1 = g_hb1 + (size_t)row * HDIM_;

    int mp[8];
    *(int4*)&mp[0] = *(const int4*)&mrow[tid * 8];
    *(int4*)&mp[4] = *(const int4*)&mrow[tid * 8 + 4];

    __nv_bfloat16 b0[8], b1[8];
    float mn[8];
#pragma unroll
    for (int j = 0; j < 8; ++j) {
        bool share, cur;
        if (lpos[j] >= 0) {
            const int f = s_csel[lpos[j]];
            share = (f & 1) != 0;
            cur   = (f & 2) != 0;
        } else {
            share = v2[j] > T0 + e0;
            cur   = v2[j] > T1 + e1;
        }
        const float mv = share ? v[j] : 0.f;
        b0[j] = __float2bfloat16_rn(mv);
        b1[j] = __float2bfloat16_rn(mv - __bfloat162float(b0[j]));
        mn[j] = (float)mp[j] + (cur ? 1.f : 0.f);
    }
    *(uint4*)&hb0[tid * 8]       = *(uint4*)b0;
    *(uint4*)&hb1[tid * 8]       = *(uint4*)b1;
    *(float4*)&nrow[tid * 8]     = *(float4*)&mn[0];
    *(float4*)&nrow[tid * 8 + 4] = *(float4*)&mn[4];
}

extern "C" void kernel_launch(void* const* d_in, const int* in_sizes, int n_in,
                              void* d_out, int out_size)
{
    const float* x      = (const float*)d_in[0];
    const int*   mask_p = (const int*)  d_in[1];
    const float* W_enc  = (const float*)d_in[2];
    const float* b_enc  = (const float*)d_in[3];
    const float* W_dec  = (const float*)d_in[4];
    const float* b_dec  = (const float*)d_in[5];

    float* out      = (float*)d_out;
    float* mask_new = out + (size_t)M_TOT * ODIM_;

    float* hbuf;
    __nv_bfloat16 *hb0, *hb1, *xb0, *xb1, *we0, *we1, *wd0, *wd1;
    cudaGetSymbolAddress((void**)&hbuf, g_h);
    cudaGetSymbolAddress((void**)&hb0,  g_hb0);
    cudaGetSymbolAddress((void**)&hb1,  g_hb1);
    cudaGetSymbolAddress((void**)&xb0,  g_xb0);
    cudaGetSymbolAddress((void**)&xb1,  g_xb1);
    cudaGetSymbolAddress((void**)&we0,  g_we0);
    cudaGetSymbolAddress((void**)&we1,  g_we1);
    cudaGetSymbolAddress((void**)&wd0,  g_wd0);
    cudaGetSymbolAddress((void**)&wd1,  g_wd1);

    cudaFuncSetAttribute(gemm_bf3<true>,  cudaFuncAttributeMaxDynamicSharedMemorySize, SMEM_GG);
    cudaFuncSetAttribute(gemm_bf3<false>, cudaFuncAttributeMaxDynamicSharedMemorySize, SMEM_GG);

    // fused splits: 4096 blocks x, 512 W_enc, 512 W_dec
    split_all<<<5120, 256>>>(x, xb0, xb1, W_enc, we0, we1, W_dec, wd0, wd1);

    // encoder: h~ = x @ W_enc^T + b_enc, zero where mask_prev>0 (bf16 3-product)
    gemm_bf3<true ><<<dim3(HDIM_ / 128, M_TOT / 128), 256, SMEM_GG>>>(
        xb0, xb1, we0, we1, b_enc, mask_p, hbuf, M_TOT, HDIM_, IDIM_);

    // exact dual top-k with band repair; emits mask_new + masked-h bf16 planes
    topk_band<<<M_TOT, 256>>>(mask_p, mask_new, x, W_enc, b_enc);

    // decoder: out = h_masked @ W_dec^T + b_dec
    gemm_bf3<false><<<dim3(ODIM_ / 128, M_TOT / 128), 256, SMEM_GG>>>(
        hb0, hb1, wd0, wd1, b_dec, nullptr, out, M_TOT, ODIM_, HDIM_);
}